// round 17
// baseline (speedup 1.0000x reference)
#include <cuda_runtime.h>
#include <cuda_fp16.h>
#include <cstdint>

#define NTOT   12288
#define DIN    512
#define DIM    512
#define HEADS  8
#define DHEAD  64
#define NBATCH 32

// ======================= PTX helpers (sm_80 ISA, valid at compute_103) ==========
__device__ __forceinline__ uint32_t smem_u32(const void* p) {
    uint32_t a;
    asm("{ .reg .u64 t; cvta.to.shared.u64 t, %1; cvt.u32.u64 %0, t; }" : "=r"(a) : "l"(p));
    return a;
}
__device__ __forceinline__ void ldsm4(uint32_t* r, uint32_t addr) {
    asm volatile("ldmatrix.sync.aligned.m8n8.x4.shared.b16 {%0,%1,%2,%3}, [%4];"
        : "=r"(r[0]), "=r"(r[1]), "=r"(r[2]), "=r"(r[3]) : "r"(addr));
}
__device__ __forceinline__ void ldsm4t(uint32_t* r, uint32_t addr) {
    asm volatile("ldmatrix.sync.aligned.m8n8.x4.trans.shared.b16 {%0,%1,%2,%3}, [%4];"
        : "=r"(r[0]), "=r"(r[1]), "=r"(r[2]), "=r"(r[3]) : "r"(addr));
}
__device__ __forceinline__ void mma16816(float* c, const uint32_t* a,
                                         uint32_t b0, uint32_t b1) {
    asm volatile("mma.sync.aligned.m16n8k16.row.col.f32.f16.f16.f32 "
        "{%0,%1,%2,%3}, {%4,%5,%6,%7}, {%8,%9}, {%0,%1,%2,%3};"
        : "+f"(c[0]), "+f"(c[1]), "+f"(c[2]), "+f"(c[3])
        : "r"(a[0]), "r"(a[1]), "r"(a[2]), "r"(a[3]), "r"(b0), "r"(b1));
}
__device__ __forceinline__ void cpa16(uint32_t s, const void* g) {
    asm volatile("cp.async.cg.shared.global [%0], [%1], 16;" :: "r"(s), "l"(g));
}
__device__ __forceinline__ void cpa16z(uint32_t s, const void* g, bool p) {
    int sz = p ? 16 : 0;
    asm volatile("cp.async.cg.shared.global [%0], [%1], 16, %2;" :: "r"(s), "l"(g), "r"(sz));
}
#define CP_COMMIT() asm volatile("cp.async.commit_group;" ::: "memory")
#define CP_WAIT(n)  asm volatile("cp.async.wait_group %0;" :: "n"(n) : "memory")

__device__ __forceinline__ uint32_t packhi(float x, float y) {
    __half2 h = __floats2half2_rn(x, y);
    return *(uint32_t*)&h;
}

// ======================= scratch =================================================
__device__ __half g_a [NTOT * DIN];      // LN output / attention output (fp16)
__device__ __half g_wt[4 * DIN * DIM];   // [mat][n][k], single fp16
__device__ __half g_q [NTOT * DIM];
__device__ __half g_k [NTOT * DIM];
__device__ __half g_v [NTOT * DIM];
__device__ int g_starts[NBATCH + 1];

// ======================= fused prep: LN + weight transpose + starts ==============
#define LN_BLOCKS 1536
#define WC_BLOCKS 1024

__global__ void __launch_bounds__(256)
prep_kernel(const float* __restrict__ z, const float* __restrict__ gamma,
            const float* __restrict__ beta,
            const float* __restrict__ Wq, const float* __restrict__ Wk,
            const float* __restrict__ Wv, const float* __restrict__ Wo,
            const int* __restrict__ src) {
    __shared__ float t[32][33];
    const int blk = blockIdx.x;
    const int tid = threadIdx.x;

    if (blk < LN_BLOCKS) {
        const int row  = blk * 8 + (tid >> 5);
        const int lane = tid & 31;
        const float* zr = z + (size_t)row * DIN;
        float4 v[4];
        float s = 0.f, ss = 0.f;
        #pragma unroll
        for (int i = 0; i < 4; i++) {
            v[i] = ((const float4*)zr)[lane + i * 32];
            s  += v[i].x + v[i].y + v[i].z + v[i].w;
            ss += v[i].x*v[i].x + v[i].y*v[i].y + v[i].z*v[i].z + v[i].w*v[i].w;
        }
        #pragma unroll
        for (int off = 16; off; off >>= 1) {
            s  += __shfl_xor_sync(0xffffffffu, s,  off);
            ss += __shfl_xor_sync(0xffffffffu, ss, off);
        }
        const float mu  = s * (1.0f / DIN);
        const float var = ss * (1.0f / DIN) - mu * mu;
        const float inv = rsqrtf(var + 1e-5f);
        #pragma unroll
        for (int i = 0; i < 4; i++) {
            const int c4 = lane + i * 32;
            float4 g  = ((const float4*)gamma)[c4];
            float4 be = ((const float4*)beta)[c4];
            float o0 = (v[i].x - mu) * inv * g.x + be.x;
            float o1 = (v[i].y - mu) * inv * g.y + be.y;
            float o2 = (v[i].z - mu) * inv * g.z + be.z;
            float o3 = (v[i].w - mu) * inv * g.w + be.w;
            size_t base = (size_t)row * DIN + c4 * 4;
            *(uint32_t*)&g_a[base]     = packhi(o0, o1);
            *(uint32_t*)&g_a[base + 2] = packhi(o2, o3);
        }
    } else if (blk < LN_BLOCKS + WC_BLOCKS) {
        const int w = blk - LN_BLOCKS;
        const int bx = w & 15;
        const int by = (w >> 4) & 15;
        const int mz = w >> 8;
        const float* W = mz == 0 ? Wq : mz == 1 ? Wk : mz == 2 ? Wv : Wo;
        const int tx = tid & 31, ty = tid >> 5;
        #pragma unroll
        for (int i = 0; i < 4; i++)
            t[ty + 8 * i][tx] = W[(size_t)(by * 32 + ty + 8 * i) * DIM + bx * 32 + tx];
        __syncthreads();
        size_t mbase = (size_t)mz * DIN * DIM;
        #pragma unroll
        for (int i = 0; i < 4; i++) {
            int n = bx * 32 + ty + 8 * i;
            int k = by * 32 + tx;
            g_wt[mbase + (size_t)n * DIN + k] = __float2half(t[tx][ty + 8 * i]);
        }
    } else {
        int b = tid;
        if (b <= NBATCH) {
            int lo = 0, hi = NTOT;
            while (lo < hi) { int mid = (lo + hi) >> 1; if (src[mid] < b) lo = mid + 1; else hi = mid; }
            g_starts[b] = lo;
        }
    }
}

// ======================= fp16 GEMM: 4 warps, 64x64 warp tiles, 3-stage cp.async ==
// C = A @ W   CTA tile 128x128, k-chunk 64, 128 threads, 2 CTAs/SM.
// Single-product frees registers -> 64x64 warp tile (acc 128 + frags ~20 regs)
// halves smem crossbar bytes/MMA: LDS 1000 cyc ~ HMMA 1024 cyc per SM per chunk.
#define GLDS 72
#define G_TILE_B  (128 * GLDS * 2)     // 18432 B per tile
#define G_STAGE_B (2 * G_TILE_B)       // 36864 B per stage
#define G_SMEM_TOT (3 * G_STAGE_B)     // 110592 B -> 2 CTAs/SM (221 KB <= 228)

// EPI 0: write fp16 per-mat.  EPI 1: write fp32 + bias.
template<int EPI>
__global__ void __launch_bounds__(128, 2)
gemm_mma(const __half* __restrict__ A, const __half* __restrict__ Wt,
         __half* o0, __half* o1, __half* o2,
         float* fout, const float* __restrict__ bias) {
    extern __shared__ char smem[];
    const uint32_t sb = smem_u32(smem);
    const int tid  = threadIdx.x;
    const int wid  = tid >> 5;           // 0..3
    const int lane = tid & 31;
    const int mwarp = wid & 1;           // warp m offset = mwarp*64
    const int nwarp = wid >> 1;          // warp n offset = nwarp*64
    const int nBase = blockIdx.x * 128;
    const int mBase = blockIdx.y * 128;
    const int mat = blockIdx.z;
    const int lrow = lane & 15;
    const int lcol = (lane >> 4) * 8;

    __half* ohp = (mat == 0) ? o0 : (mat == 1) ? o1 : o2;

    const __half* gsrc[2] = {
        A + (size_t)mBase * DIN,
        Wt + (size_t)mat * DIN * DIM + (size_t)nBase * DIN };

    float acc[4][8][4];
    #pragma unroll
    for (int a = 0; a < 4; a++)
        #pragma unroll
        for (int b = 0; b < 8; b++)
            #pragma unroll
            for (int c = 0; c < 4; c++) acc[a][b][c] = 0.f;

    // stage loader: 2 tiles x [128 rows x 64 fp16]; 16 cp.async per thread
    auto load_chunk = [&](int st, int kb) {
        const uint32_t sbase = sb + st * G_STAGE_B;
        #pragma unroll
        for (int t = 0; t < 2; t++) {
            #pragma unroll
            for (int r = 0; r < 8; r++) {
                int idx = tid + r * 128;          // 0..1023
                int row = idx >> 3;               // 0..127
                int j   = idx & 7;                // 16B units
                cpa16(sbase + t * G_TILE_B + row * (GLDS * 2) + j * 16,
                      gsrc[t] + kb + (size_t)row * DIN + j * 8);
            }
        }
    };

    load_chunk(0, 0);  CP_COMMIT();
    load_chunk(1, 64); CP_COMMIT();

    for (int chunk = 0; chunk < 8; chunk++) {
        if (chunk < 7) { CP_WAIT(1); }
        else           { CP_WAIT(0); }
        __syncthreads();
        if (chunk < 6) { load_chunk((chunk + 2) % 3, (chunk + 2) * 64); CP_COMMIT(); }
        const uint32_t sbs = sb + (chunk % 3) * G_STAGE_B;

        #pragma unroll
        for (int ks = 0; ks < 4; ks++) {
            const int kk = ks * 16 + lcol;
            uint32_t ah[4][4];
            #pragma unroll
            for (int mt = 0; mt < 4; mt++) {
                uint32_t off = (uint32_t)((mwarp * 64 + mt * 16 + lrow) * GLDS + kk) * 2;
                ldsm4(ah[mt], sbs + off);
            }
            #pragma unroll
            for (int nb = 0; nb < 4; nb++) {
                uint32_t off = (uint32_t)((nwarp * 64 + nb * 16 + lrow) * GLDS + kk) * 2;
                uint32_t wv[4];
                ldsm4(wv, sbs + G_TILE_B + off);
                #pragma unroll
                for (int mt = 0; mt < 4; mt++) {
                    mma16816(acc[mt][2 * nb],     ah[mt], wv[0], wv[2]);
                    mma16816(acc[mt][2 * nb + 1], ah[mt], wv[1], wv[3]);
                }
            }
        }
        // single sync per chunk: next iteration's sync is the barrier
    }

    const int erow = lane >> 2;
    const int ecol = (lane & 3) * 2;
    #pragma unroll
    for (int mt = 0; mt < 4; mt++) {
        int r0 = mBase + mwarp * 64 + mt * 16 + erow;
        #pragma unroll
        for (int n8 = 0; n8 < 8; n8++) {
            int col = nBase + nwarp * 64 + n8 * 8 + ecol;
            float c0 = acc[mt][n8][0], c1 = acc[mt][n8][1];
            float c2 = acc[mt][n8][2], c3 = acc[mt][n8][3];
            if (EPI == 1) {
                float2 bb = *(const float2*)&bias[col];
                *(float2*)&fout[(size_t)r0 * DIM + col]       = make_float2(c0 + bb.x, c1 + bb.y);
                *(float2*)&fout[(size_t)(r0 + 8) * DIM + col] = make_float2(c2 + bb.x, c3 + bb.y);
            } else {
                *(uint32_t*)&ohp[(size_t)r0 * DIM + col]       = packhi(c0, c1);
                *(uint32_t*)&ohp[(size_t)(r0 + 8) * DIM + col] = packhi(c2, c3);
            }
        }
    }
}

// ======================= tensor-core flash attention (single-product fp16) =======
#define AP 72
#define AT_B (64 * AP * 2)                 // 9216
#define A_SMEM (AT_B + 2 * 2 * AT_B)       // 46080: Q + 2 stages x (K,V)

__global__ void __launch_bounds__(128)
attn_kernel(const __half* __restrict__ q, const __half* __restrict__ k,
            const __half* __restrict__ v, __half* __restrict__ oout) {
    extern __shared__ char smem[];
    const uint32_t sb = smem_u32(smem);
    const int qt = blockIdx.x, h = blockIdx.y, b = blockIdx.z;
    const int s0 = g_starts[b];
    const int ng = g_starts[b + 1] - s0;
    const int q0 = qt * 64;
    if (q0 >= ng) return;
    const int tid = threadIdx.x;
    const int w = tid >> 5, lane = tid & 31;
    const int lrow = lane & 15, lcol = (lane >> 4) * 8;

    const uint32_t sQ = sb;

    {
        const size_t gb = (size_t)(s0 + q0) * DIM + h * DHEAD;
        #pragma unroll
        for (int r = 0; r < 4; r++) {
            int idx = tid + r * 128;
            int m = idx >> 3, j = idx & 7;
            bool p = (q0 + m) < ng;
            cpa16z(sQ + (uint32_t)(m * AP + j * 8) * 2, q + gb + (size_t)m * DIM + j * 8, p);
        }
    }

    const __half* kvsrc[2] = { k, v };
    auto load_kv = [&](int st, int kb) {
        uint32_t sbase = sb + AT_B + st * 2 * AT_B;
        const size_t gb = (size_t)(s0 + kb) * DIM + h * DHEAD;
        #pragma unroll
        for (int t = 0; t < 2; t++)
            #pragma unroll
            for (int r = 0; r < 4; r++) {
                int idx = tid + r * 128;
                int m = idx >> 3, j = idx & 7;
                bool p = (kb + m) < ng;
                cpa16z(sbase + t * AT_B + (uint32_t)(m * AP + j * 8) * 2,
                       kvsrc[t] + gb + (size_t)m * DIM + j * 8, p);
            }
    };

    load_kv(0, 0); CP_COMMIT();

    float sv[8][4], ov[8][4];
    #pragma unroll
    for (int j = 0; j < 8; j++)
        #pragma unroll
        for (int c = 0; c < 4; c++) ov[j][c] = 0.f;
    float rm0 = -1e30f, rm1 = -1e30f, rl0 = 0.f, rl1 = 0.f;

    const int nchunks = (ng + 63) >> 6;
    for (int c = 0; c < nchunks; c++) {
        if (c + 1 < nchunks) { load_kv((c + 1) & 1, (c + 1) * 64); CP_COMMIT(); CP_WAIT(1); }
        else                 { CP_WAIT(0); }
        __syncthreads();
        const uint32_t sK = sb + AT_B + (c & 1) * 2 * AT_B;
        const uint32_t sV = sK + AT_B;

        #pragma unroll
        for (int j = 0; j < 8; j++)
            #pragma unroll
            for (int cc = 0; cc < 4; cc++) sv[j][cc] = 0.f;
        #pragma unroll
        for (int ks = 0; ks < 4; ks++) {
            const int kk = ks * 16 + lcol;
            uint32_t qh[4];
            ldsm4(qh, sQ + (uint32_t)((w * 16 + lrow) * AP + kk) * 2);
            #pragma unroll
            for (int n16 = 0; n16 < 4; n16++) {
                uint32_t kh[4];
                ldsm4(kh, sK + (uint32_t)((n16 * 16 + lrow) * AP + kk) * 2);
                mma16816(sv[2 * n16],     qh, kh[0], kh[2]);
                mma16816(sv[2 * n16 + 1], qh, kh[1], kh[3]);
            }
        }

        const int kb = c * 64;
        #pragma unroll
        for (int j = 0; j < 8; j++) {
            int col = kb + j * 8 + (lane & 3) * 2;
            bool v0 = col < ng, v1 = (col + 1) < ng;
            sv[j][0] = v0 ? sv[j][0] * 0.125f : -1e30f;
            sv[j][1] = v1 ? sv[j][1] * 0.125f : -1e30f;
            sv[j][2] = v0 ? sv[j][2] * 0.125f : -1e30f;
            sv[j][3] = v1 ? sv[j][3] * 0.125f : -1e30f;
        }
        float m0 = -1e30f, m1 = -1e30f;
        #pragma unroll
        for (int j = 0; j < 8; j++) {
            m0 = fmaxf(m0, fmaxf(sv[j][0], sv[j][1]));
            m1 = fmaxf(m1, fmaxf(sv[j][2], sv[j][3]));
        }
        m0 = fmaxf(m0, __shfl_xor_sync(0xffffffffu, m0, 1));
        m0 = fmaxf(m0, __shfl_xor_sync(0xffffffffu, m0, 2));
        m1 = fmaxf(m1, __shfl_xor_sync(0xffffffffu, m1, 1));
        m1 = fmaxf(m1, __shfl_xor_sync(0xffffffffu, m1, 2));
        float nm0 = fmaxf(rm0, m0), nm1 = fmaxf(rm1, m1);
        float sc0 = __expf(rm0 - nm0), sc1 = __expf(rm1 - nm1);
        rm0 = nm0; rm1 = nm1;
        float l0 = 0.f, l1 = 0.f;
        #pragma unroll
        for (int j = 0; j < 8; j++) {
            sv[j][0] = __expf(sv[j][0] - nm0); l0 += sv[j][0];
            sv[j][1] = __expf(sv[j][1] - nm0); l0 += sv[j][1];
            sv[j][2] = __expf(sv[j][2] - nm1); l1 += sv[j][2];
            sv[j][3] = __expf(sv[j][3] - nm1); l1 += sv[j][3];
        }
        l0 += __shfl_xor_sync(0xffffffffu, l0, 1);
        l0 += __shfl_xor_sync(0xffffffffu, l0, 2);
        l1 += __shfl_xor_sync(0xffffffffu, l1, 1);
        l1 += __shfl_xor_sync(0xffffffffu, l1, 2);
        rl0 = rl0 * sc0 + l0;
        rl1 = rl1 * sc1 + l1;
        #pragma unroll
        for (int j = 0; j < 8; j++) {
            ov[j][0] *= sc0; ov[j][1] *= sc0;
            ov[j][2] *= sc1; ov[j][3] *= sc1;
        }

        #pragma unroll
        for (int ks = 0; ks < 4; ks++) {
            uint32_t ah[4];
            ah[0] = packhi(sv[2 * ks][0],     sv[2 * ks][1]);
            ah[1] = packhi(sv[2 * ks][2],     sv[2 * ks][3]);
            ah[2] = packhi(sv[2 * ks + 1][0], sv[2 * ks + 1][1]);
            ah[3] = packhi(sv[2 * ks + 1][2], sv[2 * ks + 1][3]);
            #pragma unroll
            for (int d16 = 0; d16 < 4; d16++) {
                uint32_t off = (uint32_t)((ks * 16 + lrow) * AP + d16 * 16 + lcol) * 2;
                uint32_t vh[4];
                ldsm4t(vh, sV + off);
                mma16816(ov[2 * d16],     ah, vh[0], vh[1]);
                mma16816(ov[2 * d16 + 1], ah, vh[2], vh[3]);
            }
        }
        __syncthreads();
    }

    const float inv0 = 1.f / rl0, inv1 = 1.f / rl1;
    const int m0r = q0 + w * 16 + (lane >> 2);
    const bool v0 = m0r < ng, v1 = (m0r + 8) < ng;
    const size_t rb0 = (size_t)(s0 + m0r) * DIM + h * DHEAD;
    const size_t rb1 = rb0 + 8 * DIM;
    #pragma unroll
    for (int j = 0; j < 8; j++) {
        int d = j * 8 + (lane & 3) * 2;
        if (v0)
            *(uint32_t*)&oout[rb0 + d] = packhi(ov[j][0] * inv0, ov[j][1] * inv0);
        if (v1)
            *(uint32_t*)&oout[rb1 + d] = packhi(ov[j][2] * inv1, ov[j][3] * inv1);
    }
}

// ======================= launch ==================================================
extern "C" void kernel_launch(void* const* d_in, const int* in_sizes, int n_in,
                              void* d_out, int out_size) {
    const float* z     = (const float*)d_in[0];
    const int*   src   = (const int*)  d_in[1];
    const float* gamma = (const float*)d_in[2];
    const float* beta  = (const float*)d_in[3];
    const float* Wq    = (const float*)d_in[4];
    const float* Wk    = (const float*)d_in[5];
    const float* Wv    = (const float*)d_in[6];
    const float* Wo    = (const float*)d_in[7];
    const float* bo    = (const float*)d_in[8];
    float* out = (float*)d_out;

    cudaFuncSetAttribute(attn_kernel, cudaFuncAttributeMaxDynamicSharedMemorySize, A_SMEM);
    cudaFuncSetAttribute(gemm_mma<0>, cudaFuncAttributeMaxDynamicSharedMemorySize, G_SMEM_TOT);
    cudaFuncSetAttribute(gemm_mma<1>, cudaFuncAttributeMaxDynamicSharedMemorySize, G_SMEM_TOT);

    __half *a_p, *wt_p, *q_p, *k_p, *v_p;
    cudaGetSymbolAddress((void**)&a_p,  g_a);
    cudaGetSymbolAddress((void**)&wt_p, g_wt);
    cudaGetSymbolAddress((void**)&q_p,  g_q);
    cudaGetSymbolAddress((void**)&k_p,  g_k);
    cudaGetSymbolAddress((void**)&v_p,  g_v);

    // fused LN + weight convert + starts
    prep_kernel<<<LN_BLOCKS + WC_BLOCKS + 1, 256>>>(z, gamma, beta, Wq, Wk, Wv, Wo, src);

    // fused Q/K/V projections (4-warp 64x64 warp tiles, 3-stage cp.async)
    gemm_mma<0><<<dim3(4, 96, 3), 128, G_SMEM_TOT>>>(
        a_p, wt_p, q_p, k_p, v_p, nullptr, nullptr);

    attn_kernel<<<dim3(8, HEADS, NBATCH), 128, A_SMEM>>>(q_p, k_p, v_p, a_p);

    // output projection (fp32 + bias)
    gemm_mma<1><<<dim3(4, 96, 1), 128, G_SMEM_TOT>>>(
        a_p, wt_p + 3 * DIN * DIM,
        nullptr, nullptr, nullptr, out, bo);
}